// round 5
// baseline (speedup 1.0000x reference)
#include <cuda_runtime.h>
#include <cstdint>

#define KN 50000
#define KE 1600000
// C=128 channels, H=8 heads, HFD=16

// ---------------- scratch (static __device__ — no allocation allowed) ----------
__device__ __align__(16) float g_emb[KN * 128];   // 25.6 MB, mostly L2-resident during scatter
__device__ __align__(16) float g_left[KN * 8];
__device__ __align__(16) float g_right[KN * 8];
__device__ __align__(16) float g_denom[KN * 8];
__device__ int g_is64;                            // edge_index dtype flag

// ---------------- helpers ------------------------------------------------------
__device__ __forceinline__ void red_add_v4(float* addr, float4 v) {
    asm volatile("red.global.add.v4.f32 [%0], {%1,%2,%3,%4};"
                 :: "l"(addr), "f"(v.x), "f"(v.y), "f"(v.z), "f"(v.w)
                 : "memory");
}

__device__ __forceinline__ float gat_w(float e) {
    e = (e >= 0.f) ? e : 0.2f * e;   // leaky relu(0.2)
    return __expf(e);
}

__device__ __forceinline__ int load_idx(const void* ei, int is64, int pos) {
    if (is64) return (int)((const long long*)ei)[pos];
    return ((const int*)ei)[pos];
}

// ---------------- K-1: detect edge_index dtype ---------------------------------
// int64 small non-negative ids => every odd int32 word (high half) is 0.
// int32 random ids => odd words are random node ids; all-64-zero prob ~0.
__global__ void detect_kernel(const int* __restrict__ ei32) {
    int all_zero = 1;
    for (int i = 0; i < 64; i++)
        if (ei32[2 * i + 1] != 0) { all_zero = 0; break; }
    g_is64 = all_zero;
}

// ---------------- K0: out = bias, denom = 0 ------------------------------------
__global__ void init_kernel(float* __restrict__ out, const float* __restrict__ bias) {
    int i = blockIdx.x * blockDim.x + threadIdx.x;   // over KN*32 float4s
    if (i < KN * 32) {
        ((float4*)out)[i] = ((const float4*)bias)[i & 31];
    }
    if (i < KN * 2) {  // KN*8/4 float4s of denom
        ((float4*)g_denom)[i] = make_float4(0.f, 0.f, 0.f, 0.f);
    }
}

// ---------------- K1: emb = X @ W^T ; left/right = head-dots -------------------
// block = 256 threads (8 warps), 64 nodes/block, 8 nodes/warp,
// lane t owns channels 4t..4t+3 (float4 accumulators).
__global__ __launch_bounds__(256) void gemm_kernel(
    const float* __restrict__ x, const float* __restrict__ W,
    const float* __restrict__ aL, const float* __restrict__ aR)
{
    __shared__ __align__(16) float sW[32 * 132];  // W chunk transposed [kk][c], row pad 132
    __shared__ float sX[64 * 32];                 // x chunk [j][kk]

    const int tid  = threadIdx.x;
    const int lane = tid & 31;
    const int warp = tid >> 5;
    const int n0   = blockIdx.x * 64;

    float4 acc[8];
#pragma unroll
    for (int j = 0; j < 8; j++) acc[j] = make_float4(0.f, 0.f, 0.f, 0.f);

#pragma unroll 1
    for (int k0 = 0; k0 < 128; k0 += 32) {
        // stage W chunk, transposed: sW[kk][c] = W[c*128 + k0+kk]  (coalesced gmem reads)
#pragma unroll
        for (int i = 0; i < 16; i++) {
            int idx = tid + i * 256;          // 0..4095
            int c   = idx >> 5;
            int kk  = idx & 31;
            sW[kk * 132 + c] = W[c * 128 + k0 + kk];
        }
        // stage x chunk: sX[j][kk]
#pragma unroll
        for (int i = 0; i < 8; i++) {
            int idx = tid + i * 256;          // 0..2047
            int j   = idx >> 5;
            int kk  = idx & 31;
            int n   = n0 + j;
            sX[j * 32 + kk] = (n < KN) ? x[n * 128 + k0 + kk] : 0.f;
        }
        __syncthreads();

        const int jb = warp * 8;
#pragma unroll
        for (int kk = 0; kk < 32; kk++) {
            float4 wv = *(const float4*)&sW[kk * 132 + lane * 4];
#pragma unroll
            for (int j = 0; j < 8; j++) {
                float xv = sX[(jb + j) * 32 + kk];   // smem broadcast
                acc[j].x += xv * wv.x;
                acc[j].y += xv * wv.y;
                acc[j].z += xv * wv.z;
                acc[j].w += xv * wv.w;
            }
        }
        __syncthreads();
    }

    // epilogue: store emb rows; left/right via a-dot + 4-lane shfl reduce
    const int h   = lane >> 2;          // 4 lanes per head
    const int ci0 = (lane * 4) & 15;    // channel index within head
#pragma unroll
    for (int j = 0; j < 8; j++) {
        int n = n0 + warp * 8 + j;
        if (n >= KN) break;             // uniform across warp
        *(float4*)&g_emb[n * 128 + lane * 4] = acc[j];

        float pl = acc[j].x * aL[(ci0 + 0) * 8 + h] + acc[j].y * aL[(ci0 + 1) * 8 + h]
                 + acc[j].z * aL[(ci0 + 2) * 8 + h] + acc[j].w * aL[(ci0 + 3) * 8 + h];
        float pr = acc[j].x * aR[(ci0 + 0) * 8 + h] + acc[j].y * aR[(ci0 + 1) * 8 + h]
                 + acc[j].z * aR[(ci0 + 2) * 8 + h] + acc[j].w * aR[(ci0 + 3) * 8 + h];
        pl += __shfl_xor_sync(0xffffffffu, pl, 1);
        pl += __shfl_xor_sync(0xffffffffu, pl, 2);
        pr += __shfl_xor_sync(0xffffffffu, pr, 1);
        pr += __shfl_xor_sync(0xffffffffu, pr, 2);
        if ((lane & 3) == 0) {
            g_left[n * 8 + h]  = pl;
            g_right[n * 8 + h] = pr;
        }
    }
}

// ---------------- K2: denom[dst,h] += exp(leaky(left[src,h]+right[dst,h])) ----
__global__ __launch_bounds__(256) void att_denom_kernel(const void* __restrict__ ei) {
    int e = blockIdx.x * 256 + threadIdx.x;
    if (e >= KE) return;
    const int is64 = g_is64;
    int src = load_idx(ei, is64, e);
    int dst = load_idx(ei, is64, KE + e);

    float4 l0 = *(const float4*)&g_left[src * 8];
    float4 l1 = *(const float4*)&g_left[src * 8 + 4];
    float4 r0 = *(const float4*)&g_right[dst * 8];
    float4 r1 = *(const float4*)&g_right[dst * 8 + 4];

    float4 w0, w1;
    w0.x = gat_w(l0.x + r0.x); w0.y = gat_w(l0.y + r0.y);
    w0.z = gat_w(l0.z + r0.z); w0.w = gat_w(l0.w + r0.w);
    w1.x = gat_w(l1.x + r1.x); w1.y = gat_w(l1.y + r1.y);
    w1.z = gat_w(l1.z + r1.z); w1.w = gat_w(l1.w + r1.w);

    red_add_v4(&g_denom[dst * 8],     w0);
    red_add_v4(&g_denom[dst * 8 + 4], w1);
}

// ---------------- K3: out[dst] += attn * emb[src] (warp per edge, 4 edges/warp)
__global__ __launch_bounds__(256) void scatter_kernel(
    const void* __restrict__ ei, float* __restrict__ out)
{
    const int gwarp = (blockIdx.x * 256 + threadIdx.x) >> 5;
    const int lane  = threadIdx.x & 31;
    const int h     = lane >> 2;       // this lane's head
    const int e0    = gwarp * 4;
    const int is64  = g_is64;

#pragma unroll
    for (int q = 0; q < 4; q++) {
        int e = e0 + q;
        if (e >= KE) break;
        int src = load_idx(ei, is64, e);
        int dst = load_idx(ei, is64, KE + e);

        float l = g_left[src * 8 + h];
        float r = g_right[dst * 8 + h];
        float d = g_denom[dst * 8 + h];
        float a = __fdividef(gat_w(l + r), d);

        float4 v = *(const float4*)&g_emb[src * 128 + lane * 4];
        v.x *= a; v.y *= a; v.z *= a; v.w *= a;
        red_add_v4(&out[dst * 128 + lane * 4], v);
    }
}

// ---------------- launch -------------------------------------------------------
extern "C" void kernel_launch(void* const* d_in, const int* in_sizes, int n_in,
                              void* d_out, int out_size)
{
    // Bind inputs by element count (robust to metadata ordering):
    //   node_feats: 6,400,000   edge_index: 3,200,000   W: 16,384
    //   a_left / a_right / bias: 128 each (relative dict order preserved)
    const float* x    = nullptr;
    const void*  ei   = nullptr;
    const float* W    = nullptr;
    const float* p128[3] = {nullptr, nullptr, nullptr};
    int n128 = 0;
    for (int i = 0; i < n_in; i++) {
        long long sz = in_sizes[i];
        if      (sz == (long long)KN * 128) x  = (const float*)d_in[i];
        else if (sz == (long long)KE * 2)   ei = d_in[i];
        else if (sz == 128 * 128)           W  = (const float*)d_in[i];
        else if (sz == 128 && n128 < 3)     p128[n128++] = (const float*)d_in[i];
    }
    const float* aL   = p128[0];
    const float* aR   = p128[1];
    const float* bias = p128[2];
    float* out = (float*)d_out;
    (void)out_size;

    // K-1: edge_index dtype probe (int32 vs int64)
    detect_kernel<<<1, 1>>>((const int*)ei);

    // K0: out = bias, denom = 0
    init_kernel<<<(KN * 32 + 255) / 256, 256>>>(out, bias);

    // K1: emb / left / right
    gemm_kernel<<<(KN + 63) / 64, 256>>>(x, W, aL, aR);

    // K2: softmax denominators
    att_denom_kernel<<<(KE + 255) / 256, 256>>>(ei);

    // K3: weighted message scatter
    scatter_kernel<<<(KE / 4 + 7) / 8, 256>>>(ei, out);
}

// round 9
// speedup vs baseline: 1.4935x; 1.4935x over previous
#include <cuda_runtime.h>
#include <cstdint>

#define KN 50000
#define KE 1600000
#define NB 196   // ceil(KN/256) blocks for node-indexed scans
// C=128 channels, H=8 heads, HFD=16

// ---------------- scratch (static __device__ — no allocation allowed) ----------
__device__ __align__(16) float g_emb[KN * 128];   // 25.6 MB, L2-resident during gather
__device__ __align__(16) float g_left[KN * 8];
__device__ __align__(16) float g_right[KN * 8];
__device__ int   g_cnt[KN];        // per-dst edge counts
__device__ int   g_off[KN + 1];    // CSR offsets (exclusive scan, sentinel = KE)
__device__ int   g_cur[KN];        // running cursors for reorder
__device__ int   g_bsum[NB];       // block sums for scan
__device__ int   g_boff[NB];       // block offsets for scan
__device__ int   g_ssrc[KE];       // src ids sorted by dst
__device__ int   g_is64;           // edge_index dtype flag

// ---------------- helpers ------------------------------------------------------
__device__ __forceinline__ float gat_w(float e) {
    e = (e >= 0.f) ? e : 0.2f * e;   // leaky relu(0.2)
    return __expf(e);
}

__device__ __forceinline__ int load_idx(const void* ei, int is64, int pos) {
    if (is64) return (int)((const long long*)ei)[pos];
    return ((const int*)ei)[pos];
}

// ---------------- K_d: detect edge_index dtype ---------------------------------
// int64 small non-negative ids => every odd int32 word (high half) is 0.
__global__ void detect_kernel(const int* __restrict__ ei32) {
    int all_zero = 1;
    for (int i = 0; i < 64; i++)
        if (ei32[2 * i + 1] != 0) { all_zero = 0; break; }
    g_is64 = all_zero;
}

// ---------------- K_z: zero counters, set CSR sentinel --------------------------
__global__ void zero_kernel() {
    int i = blockIdx.x * blockDim.x + threadIdx.x;
    if (i < KN) g_cnt[i] = 0;
    if (i == 0) g_off[KN] = KE;
}

// ---------------- K1: emb = X @ W^T ; left/right = head-dots -------------------
__global__ __launch_bounds__(256) void gemm_kernel(
    const float* __restrict__ x, const float* __restrict__ W,
    const float* __restrict__ aL, const float* __restrict__ aR)
{
    __shared__ __align__(16) float sW[32 * 132];  // W chunk transposed [kk][c], pad 132
    __shared__ float sX[64 * 32];                 // x chunk [j][kk]

    const int tid  = threadIdx.x;
    const int lane = tid & 31;
    const int warp = tid >> 5;
    const int n0   = blockIdx.x * 64;

    float4 acc[8];
#pragma unroll
    for (int j = 0; j < 8; j++) acc[j] = make_float4(0.f, 0.f, 0.f, 0.f);

#pragma unroll 1
    for (int k0 = 0; k0 < 128; k0 += 32) {
#pragma unroll
        for (int i = 0; i < 16; i++) {
            int idx = tid + i * 256;
            int c   = idx >> 5;
            int kk  = idx & 31;
            sW[kk * 132 + c] = W[c * 128 + k0 + kk];
        }
#pragma unroll
        for (int i = 0; i < 8; i++) {
            int idx = tid + i * 256;
            int j   = idx >> 5;
            int kk  = idx & 31;
            int n   = n0 + j;
            sX[j * 32 + kk] = (n < KN) ? x[n * 128 + k0 + kk] : 0.f;
        }
        __syncthreads();

        const int jb = warp * 8;
#pragma unroll
        for (int kk = 0; kk < 32; kk++) {
            float4 wv = *(const float4*)&sW[kk * 132 + lane * 4];
#pragma unroll
            for (int j = 0; j < 8; j++) {
                float xv = sX[(jb + j) * 32 + kk];
                acc[j].x += xv * wv.x;
                acc[j].y += xv * wv.y;
                acc[j].z += xv * wv.z;
                acc[j].w += xv * wv.w;
            }
        }
        __syncthreads();
    }

    const int h   = lane >> 2;
    const int ci0 = (lane * 4) & 15;
#pragma unroll
    for (int j = 0; j < 8; j++) {
        int n = n0 + warp * 8 + j;
        if (n >= KN) break;
        *(float4*)&g_emb[n * 128 + lane * 4] = acc[j];

        float pl = acc[j].x * aL[(ci0 + 0) * 8 + h] + acc[j].y * aL[(ci0 + 1) * 8 + h]
                 + acc[j].z * aL[(ci0 + 2) * 8 + h] + acc[j].w * aL[(ci0 + 3) * 8 + h];
        float pr = acc[j].x * aR[(ci0 + 0) * 8 + h] + acc[j].y * aR[(ci0 + 1) * 8 + h]
                 + acc[j].z * aR[(ci0 + 2) * 8 + h] + acc[j].w * aR[(ci0 + 3) * 8 + h];
        pl += __shfl_xor_sync(0xffffffffu, pl, 1);
        pl += __shfl_xor_sync(0xffffffffu, pl, 2);
        pr += __shfl_xor_sync(0xffffffffu, pr, 1);
        pr += __shfl_xor_sync(0xffffffffu, pr, 2);
        if ((lane & 3) == 0) {
            g_left[n * 8 + h]  = pl;
            g_right[n * 8 + h] = pr;
        }
    }
}

// ---------------- K2: histogram of dst -----------------------------------------
__global__ __launch_bounds__(256) void hist_kernel(const void* __restrict__ ei) {
    int e = blockIdx.x * 256 + threadIdx.x;
    if (e >= KE) return;
    int dst = load_idx(ei, g_is64, KE + e);
    atomicAdd(&g_cnt[dst], 1);
}

// ---------------- K3a/b/c: exclusive scan over g_cnt (3-kernel block scan) -----
__global__ void scan1_kernel() {   // block sums
    __shared__ int s[256];
    int tid = threadIdx.x;
    int i   = blockIdx.x * 256 + tid;
    s[tid] = (i < KN) ? g_cnt[i] : 0;
    __syncthreads();
    for (int st = 128; st > 0; st >>= 1) {
        if (tid < st) s[tid] += s[tid + st];
        __syncthreads();
    }
    if (tid == 0) g_bsum[blockIdx.x] = s[0];
}

__global__ void scan2_kernel() {   // exclusive scan of NB block sums (1 block)
    __shared__ int s[256];
    int tid = threadIdx.x;
    int v = (tid < NB) ? g_bsum[tid] : 0;
    s[tid] = v;
    __syncthreads();
    for (int st = 1; st < 256; st <<= 1) {
        int t = (tid >= st) ? s[tid - st] : 0;
        __syncthreads();
        s[tid] += t;
        __syncthreads();
    }
    if (tid < NB) g_boff[tid] = s[tid] - v;   // exclusive
}

__global__ void scan3_kernel() {   // in-block exclusive scan + block offset
    __shared__ int s[256];
    int tid = threadIdx.x;
    int i   = blockIdx.x * 256 + tid;
    int v = (i < KN) ? g_cnt[i] : 0;
    s[tid] = v;
    __syncthreads();
    for (int st = 1; st < 256; st <<= 1) {
        int t = (tid >= st) ? s[tid - st] : 0;
        __syncthreads();
        s[tid] += t;
        __syncthreads();
    }
    if (i < KN) {
        int excl = s[tid] - v + g_boff[blockIdx.x];
        g_off[i] = excl;
        g_cur[i] = excl;
    }
}

// ---------------- K4: reorder src ids into dst-sorted order --------------------
__global__ __launch_bounds__(256) void reorder_kernel(const void* __restrict__ ei) {
    int e = blockIdx.x * 256 + threadIdx.x;
    if (e >= KE) return;
    const int is64 = g_is64;
    int src = load_idx(ei, is64, e);
    int dst = load_idx(ei, is64, KE + e);
    int pos = atomicAdd(&g_cur[dst], 1);
    g_ssrc[pos] = src;
}

// ---------------- K5: warp-per-dst gather: out = (Σ w·emb[src])/Σw + bias ------
__global__ __launch_bounds__(256) void gather_kernel(
    float* __restrict__ out, const float* __restrict__ bias)
{
    const int dst  = (blockIdx.x * 256 + threadIdx.x) >> 5;
    const int lane = threadIdx.x & 31;
    if (dst >= KN) return;

    const int h  = lane >> 2;      // this lane's head
    const int c4 = lane * 4;       // channel group

    const int beg = g_off[dst];
    const int end = g_off[dst + 1];
    const float rh = g_right[dst * 8 + h];

    float4 acc = make_float4(0.f, 0.f, 0.f, 0.f);
    float  wsum = 0.f;

    for (int base = beg; base < end; base += 32) {
        int n = end - base; if (n > 32) n = 32;
        int mysrc = (lane < n) ? g_ssrc[base + lane] : 0;
#pragma unroll 4
        for (int j = 0; j < n; j++) {
            int src = __shfl_sync(0xffffffffu, mysrc, j);
            float w = gat_w(g_left[src * 8 + h] + rh);
            wsum += w;
            float4 v = *(const float4*)&g_emb[src * 128 + c4];
            acc.x += w * v.x;
            acc.y += w * v.y;
            acc.z += w * v.z;
            acc.w += w * v.w;
        }
    }

    float inv = (end > beg) ? __fdividef(1.f, wsum) : 0.f;
    float4 b = *(const float4*)&bias[c4];
    float4 o;
    o.x = acc.x * inv + b.x;
    o.y = acc.y * inv + b.y;
    o.z = acc.z * inv + b.z;
    o.w = acc.w * inv + b.w;
    *(float4*)&out[dst * 128 + c4] = o;
}

// ---------------- launch -------------------------------------------------------
extern "C" void kernel_launch(void* const* d_in, const int* in_sizes, int n_in,
                              void* d_out, int out_size)
{
    // Bind inputs by element count (robust to metadata ordering):
    //   node_feats: 6,400,000   edge_index: 3,200,000   W: 16,384
    //   a_left / a_right / bias: 128 each (relative dict order preserved)
    const float* x    = nullptr;
    const void*  ei   = nullptr;
    const float* W    = nullptr;
    const float* p128[3] = {nullptr, nullptr, nullptr};
    int n128 = 0;
    for (int i = 0; i < n_in; i++) {
        long long sz = in_sizes[i];
        if      (sz == (long long)KN * 128) x  = (const float*)d_in[i];
        else if (sz == (long long)KE * 2)   ei = d_in[i];
        else if (sz == 128 * 128)           W  = (const float*)d_in[i];
        else if (sz == 128 && n128 < 3)     p128[n128++] = (const float*)d_in[i];
    }
    const float* aL   = p128[0];
    const float* aR   = p128[1];
    const float* bias = p128[2];
    float* out = (float*)d_out;
    (void)out_size;

    detect_kernel<<<1, 1>>>((const int*)ei);
    zero_kernel<<<NB, 256>>>();
    hist_kernel<<<(KE + 255) / 256, 256>>>(ei);
    gemm_kernel<<<(KN + 63) / 64, 256>>>(x, W, aL, aR);
    scan1_kernel<<<NB, 256>>>();
    scan2_kernel<<<1, 256>>>();
    scan3_kernel<<<NB, 256>>>();
    reorder_kernel<<<(KE + 255) / 256, 256>>>(ei);
    gather_kernel<<<(KN * 32 + 255) / 256, 256>>>(out, bias);
}